// round 2
// baseline (speedup 1.0000x reference)
#include <cuda_runtime.h>

typedef unsigned long long u64;

#define THREADS 256
#define NP 50000            // N (points per batch row), fixed by the problem
#define HID 128

// ---- shared-memory layout (in floats) ----
#define SM_W2H 0            // 128*128
#define SM_W2G 16384        // 128*128
#define SM_W1H 32768        // 128*4
#define SM_W1G 33280        // 128*4
#define SM_B1H 33792        // 128
#define SM_B1G 33920        // 128
#define SM_B2H 34048        // 128
#define SM_B2G 34176        // 128
#define SM_OW  34304        // 3*128
#define SM_OB  34688        // 3
#define SM_FLOATS 34692
#define SM_BYTES (SM_FLOATS * 4)

__device__ __forceinline__ u64 ffma2(u64 a, u64 b, u64 c) {
    u64 d;
    asm("fma.rn.f32x2 %0, %1, %2, %3;" : "=l"(d) : "l"(a), "l"(b), "l"(c));
    return d;
}
__device__ __forceinline__ u64 pack2(float lo, float hi) {
    u64 r;
    asm("mov.b64 %0, {%1, %2};" : "=l"(r) : "f"(lo), "f"(hi));
    return r;
}
__device__ __forceinline__ void unpack2(u64 v, float& lo, float& hi) {
    asm("mov.b64 {%0, %1}, %2;" : "=f"(lo), "=f"(hi) : "l"(v));
}
__device__ __forceinline__ float sigmoid_f(float x) {
    return __fdividef(1.0f, 1.0f + __expf(-x));
}

__global__ void __launch_bounds__(THREADS, 1)
node_rk4_kernel(const float* __restrict__ x0,
                const float* __restrict__ h1w, const float* __restrict__ h1b,
                const float* __restrict__ g1w, const float* __restrict__ g1b,
                const float* __restrict__ h2w, const float* __restrict__ h2b,
                const float* __restrict__ g2w, const float* __restrict__ g2b,
                const float* __restrict__ ow,  const float* __restrict__ ob,
                float* __restrict__ out, int B, int N)
{
    extern __shared__ float sm[];
    const int tid = threadIdx.x;

    // ---- cooperative weight staging (per-CTA, hits L2 after wave 1) ----
    for (int i = tid; i < HID * HID; i += THREADS) {
        sm[SM_W2H + i] = h2w[i];
        sm[SM_W2G + i] = g2w[i];
    }
    for (int i = tid; i < HID * 4; i += THREADS) {
        sm[SM_W1H + i] = h1w[i];
        sm[SM_W1G + i] = g1w[i];
    }
    for (int i = tid; i < HID; i += THREADS) {
        sm[SM_B1H + i] = h1b[i];
        sm[SM_B1G + i] = g1b[i];
        sm[SM_B2H + i] = h2b[i];
        sm[SM_B2G + i] = g2b[i];
    }
    for (int i = tid; i < 3 * HID; i += THREADS) sm[SM_OW + i] = ow[i];
    if (tid < 3) sm[SM_OB + tid] = ob[tid];
    __syncthreads();

    const int P = B * N;
    const int p = blockIdx.x * THREADS + tid;
    if (p >= P) return;
    const int b = p / N;
    const int n = p - b * N;

    const float* xb = x0 + (size_t)b * 3 * N + n;
    float x0r0 = xb[0];
    float x0r1 = xb[N];
    float x0r2 = xb[2 * N];

    // vectorized views of layer-2 weights (row = 128 floats = 32 ulonglong2)
    const ulonglong2* w2h_v = (const ulonglong2*)(sm + SM_W2H);
    const ulonglong2* w2g_v = (const ulonglong2*)(sm + SM_W2G);
    const float4* w1h4 = (const float4*)(sm + SM_W1H);
    const float4* w1g4 = (const float4*)(sm + SM_W1G);

    float k10 = 0.f, k11 = 0.f, k12 = 0.f;
    float k20 = 0.f, k21 = 0.f, k22 = 0.f;
    float k30 = 0.f, k31 = 0.f, k32 = 0.f;
    float r0 = 0.f, r1 = 0.f, r2 = 0.f;

    const float third = 1.0f / 3.0f;

    #pragma unroll 1
    for (int s = 0; s < 4; ++s) {
        // ---- RK 3/8-rule stage input ----
        float xin0, xin1, xin2, tt;
        if (s == 0) {
            xin0 = x0r0; xin1 = x0r1; xin2 = x0r2; tt = 0.0f;
        } else if (s == 1) {
            xin0 = fmaf(k10, third, x0r0);
            xin1 = fmaf(k11, third, x0r1);
            xin2 = fmaf(k12, third, x0r2);
            tt = third;
        } else if (s == 2) {
            xin0 = x0r0 + k20 - k10 * third;
            xin1 = x0r1 + k21 - k11 * third;
            xin2 = x0r2 + k22 - k12 * third;
            tt = third * 2.0f;
        } else {
            xin0 = x0r0 + k10 - k20 + k30;
            xin1 = x0r1 + k11 - k21 + k31;
            xin2 = x0r2 + k12 - k22 + k32;
            tt = 1.0f;
        }

        // ---- layer 1: z1[c] = relu(h1 * sigmoid(g1)), packed in pairs ----
        u64 z1[HID / 2];
        #pragma unroll
        for (int c = 0; c < HID; c += 2) {
            float4 whA = w1h4[c], whB = w1h4[c + 1];
            float4 wgA = w1g4[c], wgB = w1g4[c + 1];
            float hA = fmaf(whA.x, xin0, fmaf(whA.y, xin1,
                       fmaf(whA.z, xin2, fmaf(whA.w, tt, sm[SM_B1H + c]))));
            float hB = fmaf(whB.x, xin0, fmaf(whB.y, xin1,
                       fmaf(whB.z, xin2, fmaf(whB.w, tt, sm[SM_B1H + c + 1]))));
            float gA = fmaf(wgA.x, xin0, fmaf(wgA.y, xin1,
                       fmaf(wgA.z, xin2, fmaf(wgA.w, tt, sm[SM_B1G + c]))));
            float gB = fmaf(wgB.x, xin0, fmaf(wgB.y, xin1,
                       fmaf(wgB.z, xin2, fmaf(wgB.w, tt, sm[SM_B1G + c + 1]))));
            float zA = fmaxf(hA * sigmoid_f(gA), 0.0f);
            float zB = fmaxf(hB * sigmoid_f(gB), 0.0f);
            z1[c >> 1] = pack2(zA, zB);
        }

        // ---- layer 2 fused with output projection (z2 never materialized) ----
        float o0 = 0.f, o1 = 0.f, o2 = 0.f;
        for (int o = 0; o < HID; o += 2) {
            const ulonglong2* rh = w2h_v + (o << 5);   // row o (32 ulonglong2/row)
            const ulonglong2* rg = w2g_v + (o << 5);
            u64 ah0 = 0ull, ag0 = 0ull, ah1 = 0ull, ag1 = 0ull;
            #pragma unroll
            for (int ii = 0; ii < 32; ++ii) {
                ulonglong2 wh0 = rh[ii];
                ulonglong2 wh1 = rh[ii + 32];
                ulonglong2 wg0 = rg[ii];
                ulonglong2 wg1 = rg[ii + 32];
                u64 za = z1[2 * ii];
                u64 zb = z1[2 * ii + 1];
                ah0 = ffma2(wh0.x, za, ah0); ah0 = ffma2(wh0.y, zb, ah0);
                ah1 = ffma2(wh1.x, za, ah1); ah1 = ffma2(wh1.y, zb, ah1);
                ag0 = ffma2(wg0.x, za, ag0); ag0 = ffma2(wg0.y, zb, ag0);
                ag1 = ffma2(wg1.x, za, ag1); ag1 = ffma2(wg1.y, zb, ag1);
            }
            float lo, hi;
            unpack2(ah0, lo, hi); float h0 = lo + hi + sm[SM_B2H + o];
            unpack2(ag0, lo, hi); float g0 = lo + hi + sm[SM_B2G + o];
            unpack2(ah1, lo, hi); float h1 = lo + hi + sm[SM_B2H + o + 1];
            unpack2(ag1, lo, hi); float g1 = lo + hi + sm[SM_B2G + o + 1];
            float z20 = fmaxf(h0 * sigmoid_f(g0), 0.0f);
            float z21 = fmaxf(h1 * sigmoid_f(g1), 0.0f);
            o0 = fmaf(sm[SM_OW + o],            z20, o0);
            o0 = fmaf(sm[SM_OW + o + 1],        z21, o0);
            o1 = fmaf(sm[SM_OW + HID + o],      z20, o1);
            o1 = fmaf(sm[SM_OW + HID + o + 1],  z21, o1);
            o2 = fmaf(sm[SM_OW + 2*HID + o],    z20, o2);
            o2 = fmaf(sm[SM_OW + 2*HID + o + 1],z21, o2);
        }

        float v0 = tanhf(o0 + sm[SM_OB + 0]) * 0.5f;
        float v1 = tanhf(o1 + sm[SM_OB + 1]) * 0.5f;
        float v2 = tanhf(o2 + sm[SM_OB + 2]) * 0.5f;

        if (s == 0)      { k10 = v0; k11 = v1; k12 = v2; }
        else if (s == 1) { k20 = v0; k21 = v1; k22 = v2; }
        else if (s == 2) { k30 = v0; k31 = v1; k32 = v2; }
        else {
            r0 = x0r0 + 0.125f * (k10 + 3.0f * (k20 + k30) + v0);
            r1 = x0r1 + 0.125f * (k11 + 3.0f * (k21 + k31) + v1);
            r2 = x0r2 + 0.125f * (k12 + 3.0f * (k22 + k32) + v2);
        }
    }

    float* op = out + (size_t)b * 3 * N + n;
    op[0]     = r0;
    op[N]     = r1;
    op[2 * N] = r2;
}

extern "C" void kernel_launch(void* const* d_in, const int* in_sizes, int n_in,
                              void* d_out, int out_size)
{
    const float* x0  = (const float*)d_in[0];
    const float* h1w = (const float*)d_in[1];
    const float* h1b = (const float*)d_in[2];
    const float* g1w = (const float*)d_in[3];
    const float* g1b = (const float*)d_in[4];
    const float* h2w = (const float*)d_in[5];
    const float* h2b = (const float*)d_in[6];
    const float* g2w = (const float*)d_in[7];
    const float* g2b = (const float*)d_in[8];
    const float* ow  = (const float*)d_in[9];
    const float* ob  = (const float*)d_in[10];
    float* out = (float*)d_out;

    const int N = NP;
    const int B = in_sizes[0] / (3 * N);
    const int P = B * N;

    cudaFuncSetAttribute(node_rk4_kernel,
                         cudaFuncAttributeMaxDynamicSharedMemorySize, SM_BYTES);

    const int blocks = (P + THREADS - 1) / THREADS;
    node_rk4_kernel<<<blocks, THREADS, SM_BYTES>>>(
        x0, h1w, h1b, g1w, g1b, h2w, h2b, g2w, g2b, ow, ob, out, B, N);
}